// round 4
// baseline (speedup 1.0000x reference)
#include <cuda_runtime.h>

// MedianBlur: out = x + 0.2*(median3x3(x, zero-pad) - x)
// x: (8, 64, 256, 256) fp32 -> 512 independent 256x256 images.
// 1 warp = 8-row x 128-col tile; each lane owns 4 columns (one float4).
// Low register footprint (~50) so 5 blocks/SM resident (62.5% occ cap).
// Horizontal halo: warp shuffle + 2 predicated scalar LDGs (lanes 0/31,
// issued one row ahead with the float4 prefetch, so latency is hidden).

#define H 256
#define W 256
#define RPW 8
#define RES_SCALE 0.2f

struct Pre { float4 v; float lf, rt; };

__device__ __forceinline__ Pre load_pre(const float* __restrict__ img,
                                        int g, int x0, int lane) {
    Pre p;
    if (g >= 0 && g < H) {               // uniform branch (g same across warp)
        const float* row = img + g * W;
        p.v = *reinterpret_cast<const float4*>(row + x0);
        p.lf = 0.f;
        p.rt = 0.f;
        if (lane == 0 && x0 > 0)       p.lf = row[x0 - 1];   // cross-warp halo
        if (lane == 31 && x0 + 4 < W)  p.rt = row[x0 + 4];
    } else {
        p.v = make_float4(0.f, 0.f, 0.f, 0.f);
        p.lf = 0.f;
        p.rt = 0.f;
    }
    return p;
}

__device__ __forceinline__ void finish(const Pre& p, int lane, float r[6]) {
    r[1] = p.v.x; r[2] = p.v.y; r[3] = p.v.z; r[4] = p.v.w;
    float lf = __shfl_up_sync(0xffffffffu, p.v.w, 1);
    float rt = __shfl_down_sync(0xffffffffu, p.v.x, 1);
    r[0] = (lane == 0)  ? p.lf : lf;
    r[5] = (lane == 31) ? p.rt : rt;
}

// exact (min, med, max) of 3
__device__ __forceinline__ void sort3(float x0, float x1, float x2,
                                      float& mn, float& md, float& mx) {
    float lo = fminf(x0, x1);
    float hi = fmaxf(x0, x1);
    mn = fminf(lo, x2);
    md = fminf(fmaxf(x2, lo), hi);
    mx = fmaxf(hi, x2);
}

__device__ __forceinline__ float med3(float a, float b, float c) {
    float lo = fminf(a, b), hi = fmaxf(a, b);
    return fminf(fmaxf(c, lo), hi);
}

__global__ void __launch_bounds__(256, 5)
median_blur_kernel(const float* __restrict__ x, float* __restrict__ out) {
    const int lane = threadIdx.x & 31;
    const int wg   = blockIdx.x * (blockDim.x >> 5) + (threadIdx.x >> 5);
    const int n    = wg >> 6;            // image: 64 warp-tiles per image
    const int rem  = wg & 63;
    const int band = rem >> 1;           // 32 bands of 8 rows
    const int half = rem & 1;            // 2 column halves of 128

    const float* img = x   + (size_t)n * H * W;
    float*       o   = out + (size_t)n * H * W;
    const int y0 = band * RPW;
    const int x0 = half * 128 + lane * 4;

    float r0[6], r1[6], r2[6];
    {
        Pre t0 = load_pre(img, y0 - 1, x0, lane);
        Pre t1 = load_pre(img, y0,     x0, lane);
        finish(t0, lane, r0);
        finish(t1, lane, r1);
    }
    Pre pre = load_pre(img, y0 + 1, x0, lane);

    #pragma unroll
    for (int i = 0; i < RPW; ++i) {
        const int y = y0 + i;

        finish(pre, lane, r2);
        pre = load_pre(img, y + 2, x0, lane);   // next row (OOB -> zeros)

        float mn0, md0, mx0, mn1, md1, mx1, mn2, md2, mx2;
        sort3(r0[0], r1[0], r2[0], mn0, md0, mx0);
        sort3(r0[1], r1[1], r2[1], mn1, md1, mx1);

        float4 res;
        float* rp = &res.x;
        #pragma unroll
        for (int j = 0; j < 4; ++j) {
            sort3(r0[j + 2], r1[j + 2], r2[j + 2], mn2, md2, mx2);
            float A = fmaxf(fmaxf(mn0, mn1), mn2);
            float C = fminf(fminf(mx0, mx1), mx2);
            float B = med3(md0, md1, md2);
            float med = med3(A, B, C);
            float xc = r1[j + 1];
            rp[j] = fmaf(RES_SCALE, med - xc, xc);
            mn0 = mn1; md0 = md1; mx0 = mx1;
            mn1 = mn2; md1 = md2; mx1 = mx2;
        }

        *reinterpret_cast<float4*>(o + y * W + x0) = res;

        #pragma unroll
        for (int j = 0; j < 6; ++j) { r0[j] = r1[j]; r1[j] = r2[j]; }
    }
}

extern "C" void kernel_launch(void* const* d_in, const int* in_sizes, int n_in,
                              void* d_out, int out_size) {
    const float* x = (const float*)d_in[0];
    float* out = (float*)d_out;
    // 512 images * 64 warp-tiles = 32768 warps; 8 warps/block -> 4096 blocks
    median_blur_kernel<<<4096, 256>>>(x, out);
}